// round 12
// baseline (speedup 1.0000x reference)
#include <cuda_runtime.h>
#include <cuda_fp16.h>
#include <math.h>
#include <stdint.h>

#define Bn 16
#define Cch 128
#define HWs 3136
#define Rr 16
#define MOc 256

// ---------------- device globals ----------------
__device__ float g_a[Bn * MOc];
__device__ float g_mask[Bn * HWs];
// per-(b,tap,chunk) weight tiles, row-major 128 cout x 64 cin fp16
__device__ __align__(16) __half g_wA_hi[16 * 18 * 8192];
// pixel-major padded fp16 x: [b][y 58][x 64][cin 128]
__device__ __align__(16) __half g_xT_h[16 * 58 * 64 * 128];

// ---------------- PTX helpers (target-portable, sm_80+) ----------------
__device__ __forceinline__ uint32_t smem_u32(const void* p) {
    uint32_t a;
    asm("{ .reg .u64 t; cvta.to.shared.u64 t, %1; cvt.u32.u64 %0, t; }" : "=r"(a) : "l"(p));
    return a;
}
__device__ __forceinline__ void ldsm4(uint32_t a, uint32_t* r) {
    asm volatile("ldmatrix.sync.aligned.m8n8.x4.shared.b16 {%0,%1,%2,%3}, [%4];"
                 : "=r"(r[0]), "=r"(r[1]), "=r"(r[2]), "=r"(r[3]) : "r"(a));
}
__device__ __forceinline__ void ldsm4b(uint32_t a, uint32_t* r0, uint32_t* r1) {
    asm volatile("ldmatrix.sync.aligned.m8n8.x4.shared.b16 {%0,%1,%2,%3}, [%4];"
                 : "=r"(r0[0]), "=r"(r0[1]), "=r"(r1[0]), "=r"(r1[1]) : "r"(a));
}
__device__ __forceinline__ void ldsm2(uint32_t a, uint32_t* r) {
    asm volatile("ldmatrix.sync.aligned.m8n8.x2.shared.b16 {%0,%1}, [%2];"
                 : "=r"(r[0]), "=r"(r[1]) : "r"(a));
}
__device__ __forceinline__ void mma16816(float* c, const uint32_t* a, const uint32_t* b) {
    asm volatile("mma.sync.aligned.m16n8k16.row.col.f32.f16.f16.f32 "
                 "{%0,%1,%2,%3}, {%4,%5,%6,%7}, {%8,%9}, {%0,%1,%2,%3};"
                 : "+f"(c[0]), "+f"(c[1]), "+f"(c[2]), "+f"(c[3])
                 : "r"(a[0]), "r"(a[1]), "r"(a[2]), "r"(a[3]), "r"(b[0]), "r"(b[1]));
}
__device__ __forceinline__ void cp16(uint32_t dst, const void* src) {
    asm volatile("cp.async.cg.shared.global [%0], [%1], 16;" :: "r"(dst), "l"(src));
}
#define CP_COMMIT() asm volatile("cp.async.commit_group;" ::: "memory")
#define CP_WAIT1() asm volatile("cp.async.wait_group 1;" ::: "memory")
#define CP_WAIT0() asm volatile("cp.async.wait_group 0;" ::: "memory")

// ---------------- Kernel 0: pad + transpose + fp16 convert of x, fused mask ----------------
__global__ void __launch_bounds__(256) xT_kernel(const float* __restrict__ x,
                                                 const float* __restrict__ w_mask,
                                                 const float* __restrict__ b_mask) {
    __shared__ float s_plane[Cch][56];
    __shared__ float s_wm[Cch];
    int y = blockIdx.x;                   // padded row: img y = y-1
    int b = blockIdx.y;
    int tid = threadIdx.x;
    int yi = y - 1;
    bool yv = (unsigned)yi < 56u;
    if (tid < Cch) s_wm[tid] = w_mask[tid];
    for (int i = tid; i < Cch * 56; i += 256) {
        int c = i / 56;
        int col = i - c * 56;
        s_plane[c][col] = yv ? x[((size_t)(b * Cch + c)) * HWs + yi * 56 + col] : 0.f;
    }
    __syncthreads();

    if (yv && tid < 56) {
        float m = b_mask[0];
        #pragma unroll 16
        for (int c = 0; c < Cch; c++) m = fmaf(s_plane[c][tid], s_wm[c], m);
        g_mask[b * HWs + yi * 56 + tid] = m;
    }

    size_t rowbase = ((size_t)(b * 58 + y)) * 64 * 128;
    for (int i = tid; i < 1024; i += 256) {
        int x64 = i >> 4;
        int pc = i & 15;
        int cin0 = pc * 8;
        int ci = x64 - 1;
        bool cv = (unsigned)ci < 56u;
        unsigned int uh[4];
        #pragma unroll
        for (int q = 0; q < 4; q++) {
            unsigned int hw = 0;
            #pragma unroll
            for (int e = 0; e < 2; e++) {
                float v = cv ? s_plane[cin0 + q * 2 + e][ci] : 0.f;
                __half h = __float2half_rn(v);
                hw |= ((unsigned int)__half_as_ushort(h)) << (e * 16);
            }
            uh[q] = hw;
        }
        *(uint4*)(g_xT_h + rowbase + (size_t)x64 * 128 + cin0) = make_uint4(uh[0], uh[1], uh[2], uh[3]);
    }
}

// ---------------- Kernel 1: fused softmax + ctx (from fp16 xT) + transform + gates ----------------
// grid 16 (one block per batch), 512 threads.
__global__ void __launch_bounds__(512) ctx_kernel(const float* __restrict__ w1,
                                                  const float* __restrict__ b1,
                                                  const float* __restrict__ ln_g,
                                                  const float* __restrict__ ln_b,
                                                  const float* __restrict__ w2,
                                                  const float* __restrict__ b2) {
    __shared__ float s_att[HWs];
    __shared__ float s_red[16];
    __shared__ float s_scalar;
    __shared__ float s_part[32][130];   // [pixel-group][channel] padded
    __shared__ float s_ctx[Cch];
    __shared__ float s_t[Rr];
    int tid = threadIdx.x;
    int b = blockIdx.x;
    const float* mb = g_mask + b * HWs;

    for (int i = tid; i < HWs; i += 512) s_att[i] = mb[i];
    __syncthreads();

    float mx = -1e30f;
    for (int i = tid; i < HWs; i += 512) mx = fmaxf(mx, s_att[i]);
    #pragma unroll
    for (int o = 16; o > 0; o >>= 1) mx = fmaxf(mx, __shfl_xor_sync(0xffffffffu, mx, o));
    if ((tid & 31) == 0) s_red[tid >> 5] = mx;
    __syncthreads();
    if (tid < 32) {
        float v = (tid < 16) ? s_red[tid] : -1e30f;
        #pragma unroll
        for (int o = 8; o > 0; o >>= 1) v = fmaxf(v, __shfl_xor_sync(0xffffffffu, v, o));
        if (tid == 0) s_scalar = v;
    }
    __syncthreads();
    float gmax = s_scalar;

    float sm = 0.f;
    for (int i = tid; i < HWs; i += 512) {
        float e = expf(s_att[i] - gmax);
        s_att[i] = e;
        sm += e;
    }
    #pragma unroll
    for (int o = 16; o > 0; o >>= 1) sm += __shfl_xor_sync(0xffffffffu, sm, o);
    if ((tid & 31) == 0) s_red[tid >> 5] = sm;
    __syncthreads();
    if (tid < 32) {
        float v = (tid < 16) ? s_red[tid] : 0.f;
        #pragma unroll
        for (int o = 8; o > 0; o >>= 1) v += __shfl_xor_sync(0xffffffffu, v, o);
        if (tid == 0) s_scalar = v;
    }
    __syncthreads();
    float inv = 1.f / s_scalar;

    // ctx partials from fp16 xT (channel-contiguous, coalesced)
    int pg = tid >> 4;           // 0..31 pixel group
    int cg = tid & 15;           // 0..15 channel group (8 ch each)
    const __half* xb = g_xT_h + (size_t)b * 58 * 64 * 128;
    float acc[8];
    #pragma unroll
    for (int j = 0; j < 8; j++) acc[j] = 0.f;
    for (int p = pg; p < HWs; p += 32) {
        int yi = p / 56;
        int xi = p - yi * 56;
        const uint4 v = *(const uint4*)(xb + ((size_t)(yi + 1) * 64 + (xi + 1)) * 128 + cg * 8);
        float a = s_att[p] * inv;
        const __half2* h2 = (const __half2*)&v;
        #pragma unroll
        for (int q = 0; q < 4; q++) {
            float2 f = __half22float2(h2[q]);
            acc[2 * q] = fmaf(f.x, a, acc[2 * q]);
            acc[2 * q + 1] = fmaf(f.y, a, acc[2 * q + 1]);
        }
    }
    #pragma unroll
    for (int j = 0; j < 8; j++) s_part[pg][cg * 8 + j] = acc[j];
    __syncthreads();
    if (tid < Cch) {
        float s = 0.f;
        #pragma unroll
        for (int k = 0; k < 32; k++) s += s_part[k][tid];
        s_ctx[tid] = s;
    }
    __syncthreads();

    // transform
    if (tid < Rr) {
        float acc1 = b1[tid];
        const float* wr = w1 + tid * Cch;
        #pragma unroll 16
        for (int c = 0; c < Cch; c++) acc1 = fmaf(s_ctx[c], wr[c], acc1);
        s_t[tid] = acc1;
    }
    __syncthreads();
    if (tid == 0) {
        float mu = 0.f;
        #pragma unroll
        for (int r = 0; r < Rr; r++) mu += s_t[r];
        mu *= (1.f / Rr);
        float var = 0.f;
        #pragma unroll
        for (int r = 0; r < Rr; r++) { float d = s_t[r] - mu; var = fmaf(d, d, var); }
        var *= (1.f / Rr);
        float invs = rsqrtf(var + 1e-5f);
        #pragma unroll
        for (int r = 0; r < Rr; r++) {
            float v = (s_t[r] - mu) * invs * ln_g[r] + ln_b[r];
            s_t[r] = fmaxf(v, 0.f);
        }
    }
    __syncthreads();
    if (tid < MOc) {
        float acc2 = b2[tid];
        const float* wr = w2 + tid * Rr;
        #pragma unroll
        for (int r = 0; r < Rr; r++) acc2 = fmaf(s_t[r], wr[r], acc2);
        g_a[b * MOc + tid] = 1.f / (1.f + expf(-acc2));
    }
}

// ---------------- Kernel 2: weight-tile generation (coalesced) ----------------
__global__ void __launch_bounds__(256) prep_kernel(const float* __restrict__ w_fc,
                                                   const float* __restrict__ b_fc) {
    extern __shared__ __align__(16) char psm[];
    __half* s_h = (__half*)psm;                 // [18 tiles][16 co][64 cin]
    __shared__ float s_a[MOc];
    int cog = blockIdx.x;
    int b = blockIdx.y;
    int tid = threadIdx.x;
    int co0 = cog * 16;

    if (tid < MOc) s_a[tid] = g_a[b * MOc + tid];
    __syncthreads();

    const float* wsrc = w_fc + (size_t)co0 * 1152;
    const float* bsrc = b_fc + (size_t)co0 * 1152;
    for (int i = tid; i < 16 * 1152; i += 256) {
        int co_l = i / 1152;
        int q = i - co_l * 1152;
        int cin = q / 9;
        int tap = q - cin * 9;
        int chunk = cin >> 6;
        int cl = cin & 63;
        float av = s_a[2 * (co0 + co_l) + chunk];
        float w = fmaf(av, wsrc[i], bsrc[i]);
        s_h[(tap * 2 + chunk) * 1024 + co_l * 64 + cl] = __float2half_rn(w);
    }
    __syncthreads();

    const uint4* sh4 = (const uint4*)s_h;
    for (int i = tid; i < 2304; i += 256) {
        int tile = i >> 7;
        int rem = i & 127;
        size_t dsto = ((size_t)(b * 18 + tile)) * 8192 + (size_t)(co0 + (rem >> 3)) * 64 + (rem & 7) * 8;
        *(uint4*)(g_wA_hi + dsto) = sh4[i];
    }
}

// ---------------- Kernel 3: HMMA conv, single-term fp16, M=64 half-tiles ----------------
// grid (28 row-pair tiles, 2 cout halves, 16 batch), 128 threads, 3 CTAs/SM.
#define XT_H       0
#define A_BASE     33792
#define A_BUF_SZ   9216
#define SMEM_TOTAL 61440

__global__ void __launch_bounds__(128, 3) conv_kernel(float* __restrict__ out) {
    extern __shared__ __align__(16) char smem[];
    uint32_t su = smem_u32(smem);
    int tid = threadIdx.x;
    int wid = tid >> 5;
    int lane = tid & 31;
    int t = blockIdx.x;
    int h = blockIdx.y;
    int b = blockIdx.z;

    int grp = lane >> 3, lr = lane & 7;
    int m_base = (wid & 1) * 32;
    int rr = wid >> 1;

    uint32_t a_lane = (uint32_t)((((grp & 1) * 8 + lr) * 144) + ((grp >> 1) * 16));
    uint32_t b4_lane = (uint32_t)((((grp >> 1) * 8 + lr) * 144) + ((grp & 1) * 16));
    int l16 = lane & 15;
    uint32_t b2_lane = (uint32_t)(((l16 & 7) * 144) + (((l16 >> 3) & 1) * 16));

    float acc[2][7][4];
    #pragma unroll
    for (int mt = 0; mt < 2; mt++)
        #pragma unroll
        for (int nt = 0; nt < 7; nt++)
            #pragma unroll
            for (int e = 0; e < 4; e++) acc[mt][nt][e] = 0.f;

    auto issueA = [&](int tap, int chunk, int bf) {
        size_t srco = ((size_t)(b * 18 + tap * 2 + chunk)) * 8192 + (size_t)h * 4096;
        const char* sh = (const char*)(g_wA_hi + srco);
        uint32_t dst = su + A_BASE + bf * A_BUF_SZ;
        for (int i = tid; i < 512; i += 128) {
            uint32_t doff = (uint32_t)((i >> 3) * 144 + (i & 7) * 16);
            cp16(dst + doff, sh + i * 16);
        }
    };
    auto issueXt = [&](int chunk) {
        size_t base = (((size_t)(b * 58 + 2 * t)) * 64) * 128 + chunk * 64;
        for (int i = tid; i < 1856; i += 128) {
            int j = i >> 3;
            int pcc = i & 7;
            int r = j / 58;
            int c = j - r * 58;
            uint32_t dst = su + (uint32_t)(j * 144 + pcc * 16);
            size_t srco = base + ((size_t)r * 64 + c) * 128 + pcc * 8;
            cp16(dst, (const char*)(g_xT_h + srco));
        }
    };

    // prologue: G[A0 + Xt0], G[A1]
    issueA(0, 0, 0);
    issueXt(0);
    CP_COMMIT();
    issueA(1, 0, 1);
    CP_COMMIT();

    for (int s = 0; s < 18; s++) {
        int chunk = (s >= 9) ? 1 : 0;
        int tap = s - chunk * 9;
        int ky = tap / 3;
        int kx = tap - ky * 3;
        int buf = s % 3;

        if (s == 9) {
            // chunk switch: all warps must be done with Xt(0) before overwrite
            CP_WAIT1();
            __syncthreads();
            issueXt(1);
            issueA(2, 1, 11 % 3);        // A11 (tap 2, chunk 1)
            CP_COMMIT();
            CP_WAIT0();
            __syncthreads();
        } else if (s == 17) {
            // final step: A17 is the LAST pending group -> full drain
            CP_WAIT0();
            __syncthreads();
        } else {
            CP_WAIT1();
            __syncthreads();
            if (s < 16) {
                int s2 = s + 2;
                int ch2 = (s2 >= 9) ? 1 : 0;
                issueA(s2 - ch2 * 9, ch2, s2 % 3);
                CP_COMMIT();
            }
        }

        uint32_t AH = su + A_BASE + buf * A_BUF_SZ + (uint32_t)(m_base * 144) + a_lane;
        uint32_t brow = (uint32_t)(((rr + ky) * 58 + kx) * 144);
        uint32_t XH = su + XT_H + brow;

        #pragma unroll
        for (int k = 0; k < 4; k++) {
            uint32_t ko = (uint32_t)(k * 32);
            uint32_t ah[2][4];
            ldsm4(AH + ko, ah[0]);
            ldsm4(AH + 2304 + ko, ah[1]);
            uint32_t bh[7][2];
            #pragma unroll
            for (int jj = 0; jj < 3; jj++)
                ldsm4b(XH + b4_lane + jj * 2304 + ko, bh[2 * jj], bh[2 * jj + 1]);
            ldsm2(XH + b2_lane + 6912 + ko, bh[6]);
            #pragma unroll
            for (int mt = 0; mt < 2; mt++)
                #pragma unroll
                for (int nt = 0; nt < 7; nt++)
                    mma16816(acc[mt][nt], ah[mt], bh[nt]);
        }
    }

    __syncthreads();
    // epilogue: 64 x 112 f32 via smem
    float* s_out = (float*)smem;
    int q = lane >> 2, l = lane & 3;
    int n_base = rr * 56;
    #pragma unroll
    for (int mt = 0; mt < 2; mt++)
        #pragma unroll
        for (int nt = 0; nt < 7; nt++) {
            int row = m_base + mt * 16 + q;
            int col = n_base + nt * 8 + l * 2;
            s_out[row * 112 + col] = acc[mt][nt][0];
            s_out[row * 112 + col + 1] = acc[mt][nt][1];
            s_out[(row + 8) * 112 + col] = acc[mt][nt][2];
            s_out[(row + 8) * 112 + col + 1] = acc[mt][nt][3];
        }
    __syncthreads();
    const float4* s4 = (const float4*)s_out;
    for (int i4 = tid; i4 < 64 * 28; i4 += 128) {
        int row = i4 / 28;
        int p4 = (i4 - row * 28) * 4;
        int co = h * 64 + row;
        *(float4*)&out[((size_t)(b * Cch + co)) * HWs + t * 112 + p4] = s4[i4];
    }
}

extern "C" void kernel_launch(void* const* d_in, const int* in_sizes, int n_in,
                              void* d_out, int out_size) {
    const float* x      = (const float*)d_in[0];
    const float* w_mask = (const float*)d_in[1];
    const float* b_mask = (const float*)d_in[2];
    const float* w1     = (const float*)d_in[3];
    const float* b1     = (const float*)d_in[4];
    const float* ln_g   = (const float*)d_in[5];
    const float* ln_b   = (const float*)d_in[6];
    const float* w2     = (const float*)d_in[7];
    const float* b2     = (const float*)d_in[8];
    const float* w_fc   = (const float*)d_in[9];
    const float* b_fc   = (const float*)d_in[10];
    float* out = (float*)d_out;

    cudaFuncSetAttribute(conv_kernel, cudaFuncAttributeMaxDynamicSharedMemorySize, SMEM_TOTAL);
    cudaFuncSetAttribute(prep_kernel, cudaFuncAttributeMaxDynamicSharedMemorySize, 36864);

    xT_kernel<<<dim3(58, Bn), 256>>>(x, w_mask, b_mask);
    ctx_kernel<<<Bn, 512>>>(w1, b1, ln_g, ln_b, w2, b2);
    prep_kernel<<<dim3(8, Bn), 256, 36864>>>(w_fc, b_fc);
    conv_kernel<<<dim3(28, 2, Bn), 128, SMEM_TOTAL>>>(out);
}

// round 13
// speedup vs baseline: 1.2432x; 1.2432x over previous
#include <cuda_runtime.h>
#include <cuda_fp16.h>
#include <math.h>
#include <stdint.h>

#define Bn 16
#define Cch 128
#define HWs 3136
#define Rr 16
#define MOc 256

// ---------------- device globals ----------------
__device__ float g_part[Bn * 4 * Cch];
__device__ float g_mask[Bn * HWs];
// per-(b,tap,chunk) weight tiles, row-major 128 cout x 64 cin fp16
__device__ __align__(16) __half g_wA_hi[16 * 18 * 8192];
// pixel-major padded fp16 x: [b][y 58][x 64][cin 128]
__device__ __align__(16) __half g_xT_h[16 * 58 * 64 * 128];

// ---------------- PTX helpers (target-portable, sm_80+) ----------------
__device__ __forceinline__ uint32_t smem_u32(const void* p) {
    uint32_t a;
    asm("{ .reg .u64 t; cvta.to.shared.u64 t, %1; cvt.u32.u64 %0, t; }" : "=r"(a) : "l"(p));
    return a;
}
__device__ __forceinline__ void ldsm4(uint32_t a, uint32_t* r) {
    asm volatile("ldmatrix.sync.aligned.m8n8.x4.shared.b16 {%0,%1,%2,%3}, [%4];"
                 : "=r"(r[0]), "=r"(r[1]), "=r"(r[2]), "=r"(r[3]) : "r"(a));
}
__device__ __forceinline__ void ldsm4b(uint32_t a, uint32_t* r0, uint32_t* r1) {
    asm volatile("ldmatrix.sync.aligned.m8n8.x4.shared.b16 {%0,%1,%2,%3}, [%4];"
                 : "=r"(r0[0]), "=r"(r0[1]), "=r"(r1[0]), "=r"(r1[1]) : "r"(a));
}
__device__ __forceinline__ void ldsm2(uint32_t a, uint32_t* r) {
    asm volatile("ldmatrix.sync.aligned.m8n8.x2.shared.b16 {%0,%1}, [%2];"
                 : "=r"(r[0]), "=r"(r[1]) : "r"(a));
}
__device__ __forceinline__ void mma16816(float* c, const uint32_t* a, const uint32_t* b) {
    asm volatile("mma.sync.aligned.m16n8k16.row.col.f32.f16.f16.f32 "
                 "{%0,%1,%2,%3}, {%4,%5,%6,%7}, {%8,%9}, {%0,%1,%2,%3};"
                 : "+f"(c[0]), "+f"(c[1]), "+f"(c[2]), "+f"(c[3])
                 : "r"(a[0]), "r"(a[1]), "r"(a[2]), "r"(a[3]), "r"(b[0]), "r"(b[1]));
}
__device__ __forceinline__ void cp16(uint32_t dst, const void* src) {
    asm volatile("cp.async.cg.shared.global [%0], [%1], 16;" :: "r"(dst), "l"(src));
}
#define CP_COMMIT() asm volatile("cp.async.commit_group;" ::: "memory")
#define CP_WAIT1() asm volatile("cp.async.wait_group 1;" ::: "memory")
#define CP_WAIT0() asm volatile("cp.async.wait_group 0;" ::: "memory")

// ---------------- Kernel 0: pad + transpose + fp16 convert of x, fused mask ----------------
__global__ void __launch_bounds__(256) xT_kernel(const float* __restrict__ x,
                                                 const float* __restrict__ w_mask,
                                                 const float* __restrict__ b_mask) {
    __shared__ float s_plane[Cch][56];
    __shared__ float s_wm[Cch];
    int y = blockIdx.x;                   // padded row: img y = y-1
    int b = blockIdx.y;
    int tid = threadIdx.x;
    int yi = y - 1;
    bool yv = (unsigned)yi < 56u;
    if (tid < Cch) s_wm[tid] = w_mask[tid];
    for (int i = tid; i < Cch * 56; i += 256) {
        int c = i / 56;
        int col = i - c * 56;
        s_plane[c][col] = yv ? x[((size_t)(b * Cch + c)) * HWs + yi * 56 + col] : 0.f;
    }
    __syncthreads();

    if (yv && tid < 56) {
        float m = b_mask[0];
        #pragma unroll 16
        for (int c = 0; c < Cch; c++) m = fmaf(s_plane[c][tid], s_wm[c], m);
        g_mask[b * HWs + yi * 56 + tid] = m;
    }

    size_t rowbase = ((size_t)(b * 58 + y)) * 64 * 128;
    for (int i = tid; i < 1024; i += 256) {
        int x64 = i >> 4;
        int pc = i & 15;
        int cin0 = pc * 8;
        int ci = x64 - 1;
        bool cv = (unsigned)ci < 56u;
        unsigned int uh[4];
        #pragma unroll
        for (int q = 0; q < 4; q++) {
            unsigned int hw = 0;
            #pragma unroll
            for (int e = 0; e < 2; e++) {
                float v = cv ? s_plane[cin0 + q * 2 + e][ci] : 0.f;
                __half h = __float2half_rn(v);
                hw |= ((unsigned int)__half_as_ushort(h)) << (e * 16);
            }
            uh[q] = hw;
        }
        *(uint4*)(g_xT_h + rowbase + (size_t)x64 * 128 + cin0) = make_uint4(uh[0], uh[1], uh[2], uh[3]);
    }
}

// ---------------- Kernel 1: softmax (redundant per block) + partial ctx from fp16 xT ----------------
// grid (4 pixel strips, 16 batch), 512 threads. Coalesced all-channel reads.
__global__ void __launch_bounds__(512) ctx_kernel() {
    __shared__ float s_att[HWs];
    __shared__ float s_red[16];
    __shared__ float s_scalar;
    __shared__ float s_part[32][130];
    int tid = threadIdx.x;
    int strip = blockIdx.x;       // 0..3, pixels [strip*784, strip*784+784)
    int b = blockIdx.y;
    const float* mb = g_mask + b * HWs;

    for (int i = tid; i < HWs; i += 512) s_att[i] = mb[i];
    __syncthreads();

    float mx = -1e30f;
    for (int i = tid; i < HWs; i += 512) mx = fmaxf(mx, s_att[i]);
    #pragma unroll
    for (int o = 16; o > 0; o >>= 1) mx = fmaxf(mx, __shfl_xor_sync(0xffffffffu, mx, o));
    if ((tid & 31) == 0) s_red[tid >> 5] = mx;
    __syncthreads();
    if (tid < 32) {
        float v = (tid < 16) ? s_red[tid] : -1e30f;
        #pragma unroll
        for (int o = 8; o > 0; o >>= 1) v = fmaxf(v, __shfl_xor_sync(0xffffffffu, v, o));
        if (tid == 0) s_scalar = v;
    }
    __syncthreads();
    float gmax = s_scalar;

    float sm = 0.f;
    for (int i = tid; i < HWs; i += 512) {
        float e = expf(s_att[i] - gmax);
        s_att[i] = e;
        sm += e;
    }
    #pragma unroll
    for (int o = 16; o > 0; o >>= 1) sm += __shfl_xor_sync(0xffffffffu, sm, o);
    if ((tid & 31) == 0) s_red[tid >> 5] = sm;
    __syncthreads();
    if (tid < 32) {
        float v = (tid < 16) ? s_red[tid] : 0.f;
        #pragma unroll
        for (int o = 8; o > 0; o >>= 1) v += __shfl_xor_sync(0xffffffffu, v, o);
        if (tid == 0) s_scalar = v;
    }
    __syncthreads();
    float inv = 1.f / s_scalar;

    // partial ctx over this strip, all 128 channels, coalesced 256B/pixel
    int pg = tid >> 4;           // 0..31 pixel group
    int cg = tid & 15;           // 0..15 channel group (8 ch)
    const __half* xb = g_xT_h + (size_t)b * 58 * 64 * 128;
    int p0 = strip * 784;
    float acc[8];
    #pragma unroll
    for (int j = 0; j < 8; j++) acc[j] = 0.f;
    for (int p = p0 + pg; p < p0 + 784; p += 32) {
        int yi = p / 56;
        int xi = p - yi * 56;
        const uint4 v = *(const uint4*)(xb + ((size_t)(yi + 1) * 64 + (xi + 1)) * 128 + cg * 8);
        float a = s_att[p] * inv;
        const __half2* h2 = (const __half2*)&v;
        #pragma unroll
        for (int q = 0; q < 4; q++) {
            float2 f = __half22float2(h2[q]);
            acc[2 * q] = fmaf(f.x, a, acc[2 * q]);
            acc[2 * q + 1] = fmaf(f.y, a, acc[2 * q + 1]);
        }
    }
    #pragma unroll
    for (int j = 0; j < 8; j++) s_part[pg][cg * 8 + j] = acc[j];
    __syncthreads();
    if (tid < Cch) {
        float s = 0.f;
        #pragma unroll
        for (int k = 0; k < 32; k++) s += s_part[k][tid];
        g_part[(b * 4 + strip) * Cch + tid] = s;
    }
}

// ---------------- Kernel 2: fused transform + weight-tile generation (coalesced) ----------------
// grid (8 cout-groups of 16, 16 batch), 256 threads.
__global__ void __launch_bounds__(256) prep_kernel(const float* __restrict__ w1,
                                                   const float* __restrict__ b1,
                                                   const float* __restrict__ ln_g,
                                                   const float* __restrict__ ln_b,
                                                   const float* __restrict__ w2,
                                                   const float* __restrict__ b2,
                                                   const float* __restrict__ w_fc,
                                                   const float* __restrict__ b_fc) {
    extern __shared__ __align__(16) char psm[];
    __half* s_h = (__half*)psm;                 // [18 tiles][16 co][64 cin]
    __shared__ float s_ctx[Cch];
    __shared__ float s_t[Rr];
    __shared__ float s_a[MOc];
    int cog = blockIdx.x;
    int b = blockIdx.y;
    int tid = threadIdx.x;
    int co0 = cog * 16;

    if (tid < Cch) {
        const float* pp = g_part + b * 4 * Cch + tid;
        s_ctx[tid] = pp[0] + pp[Cch] + pp[2 * Cch] + pp[3 * Cch];
    }
    __syncthreads();
    if (tid < Rr) {
        float acc = b1[tid];
        const float* wr = w1 + tid * Cch;
        #pragma unroll 16
        for (int c = 0; c < Cch; c++) acc = fmaf(s_ctx[c], wr[c], acc);
        s_t[tid] = acc;
    }
    __syncthreads();
    if (tid == 0) {
        float mu = 0.f;
        #pragma unroll
        for (int r = 0; r < Rr; r++) mu += s_t[r];
        mu *= (1.f / Rr);
        float var = 0.f;
        #pragma unroll
        for (int r = 0; r < Rr; r++) { float d = s_t[r] - mu; var = fmaf(d, d, var); }
        var *= (1.f / Rr);
        float invs = rsqrtf(var + 1e-5f);
        #pragma unroll
        for (int r = 0; r < Rr; r++) {
            float v = (s_t[r] - mu) * invs * ln_g[r] + ln_b[r];
            s_t[r] = fmaxf(v, 0.f);
        }
    }
    __syncthreads();
    {
        float acc = b2[tid];
        const float* wr = w2 + tid * Rr;
        #pragma unroll
        for (int r = 0; r < Rr; r++) acc = fmaf(s_t[r], wr[r], acc);
        s_a[tid] = 1.f / (1.f + expf(-acc));
    }
    __syncthreads();

    const float* wsrc = w_fc + (size_t)co0 * 1152;
    const float* bsrc = b_fc + (size_t)co0 * 1152;
    for (int i = tid; i < 16 * 1152; i += 256) {
        int co_l = i / 1152;
        int q = i - co_l * 1152;
        int cin = q / 9;
        int tap = q - cin * 9;
        int chunk = cin >> 6;
        int cl = cin & 63;
        float av = s_a[2 * (co0 + co_l) + chunk];
        float w = fmaf(av, wsrc[i], bsrc[i]);
        s_h[(tap * 2 + chunk) * 1024 + co_l * 64 + cl] = __float2half_rn(w);
    }
    __syncthreads();

    const uint4* sh4 = (const uint4*)s_h;
    for (int i = tid; i < 2304; i += 256) {
        int tile = i >> 7;
        int rem = i & 127;
        size_t dsto = ((size_t)(b * 18 + tile)) * 8192 + (size_t)(co0 + (rem >> 3)) * 64 + (rem & 7) * 8;
        *(uint4*)(g_wA_hi + dsto) = sh4[i];
    }
}

// ---------------- Kernel 3: HMMA conv, single-term fp16, M=64 half-tiles ----------------
// grid (28 row-pair tiles, 2 cout halves, 16 batch), 128 threads, 3 CTAs/SM.
#define XT_H       0
#define A_BASE     33792
#define A_BUF_SZ   9216
#define SMEM_TOTAL 61440

__global__ void __launch_bounds__(128, 3) conv_kernel(float* __restrict__ out) {
    extern __shared__ __align__(16) char smem[];
    uint32_t su = smem_u32(smem);
    int tid = threadIdx.x;
    int wid = tid >> 5;
    int lane = tid & 31;
    int t = blockIdx.x;
    int h = blockIdx.y;
    int b = blockIdx.z;

    int grp = lane >> 3, lr = lane & 7;
    int m_base = (wid & 1) * 32;
    int rr = wid >> 1;

    uint32_t a_lane = (uint32_t)((((grp & 1) * 8 + lr) * 144) + ((grp >> 1) * 16));
    uint32_t b4_lane = (uint32_t)((((grp >> 1) * 8 + lr) * 144) + ((grp & 1) * 16));
    int l16 = lane & 15;
    uint32_t b2_lane = (uint32_t)(((l16 & 7) * 144) + (((l16 >> 3) & 1) * 16));

    float acc[2][7][4];
    #pragma unroll
    for (int mt = 0; mt < 2; mt++)
        #pragma unroll
        for (int nt = 0; nt < 7; nt++)
            #pragma unroll
            for (int e = 0; e < 4; e++) acc[mt][nt][e] = 0.f;

    auto issueA = [&](int tap, int chunk, int bf) {
        size_t srco = ((size_t)(b * 18 + tap * 2 + chunk)) * 8192 + (size_t)h * 4096;
        const char* sh = (const char*)(g_wA_hi + srco);
        uint32_t dst = su + A_BASE + bf * A_BUF_SZ;
        for (int i = tid; i < 512; i += 128) {
            uint32_t doff = (uint32_t)((i >> 3) * 144 + (i & 7) * 16);
            cp16(dst + doff, sh + i * 16);
        }
    };
    auto issueXt = [&](int chunk) {
        size_t base = (((size_t)(b * 58 + 2 * t)) * 64) * 128 + chunk * 64;
        for (int i = tid; i < 1856; i += 128) {
            int j = i >> 3;
            int pcc = i & 7;
            int r = j / 58;
            int c = j - r * 58;
            uint32_t dst = su + (uint32_t)(j * 144 + pcc * 16);
            size_t srco = base + ((size_t)r * 64 + c) * 128 + pcc * 8;
            cp16(dst, (const char*)(g_xT_h + srco));
        }
    };

    // prologue: G[A0 + Xt0], G[A1]
    issueA(0, 0, 0);
    issueXt(0);
    CP_COMMIT();
    issueA(1, 0, 1);
    CP_COMMIT();

    for (int s = 0; s < 18; s++) {
        int chunk = (s >= 9) ? 1 : 0;
        int tap = s - chunk * 9;
        int ky = tap / 3;
        int kx = tap - ky * 3;
        int buf = s % 3;

        if (s == 9) {
            CP_WAIT1();
            __syncthreads();
            issueXt(1);
            issueA(2, 1, 11 % 3);        // A11 (tap 2, chunk 1)
            CP_COMMIT();
            CP_WAIT0();
            __syncthreads();
        } else if (s == 17) {
            CP_WAIT0();
            __syncthreads();
        } else {
            CP_WAIT1();
            __syncthreads();
            if (s < 16) {
                int s2 = s + 2;
                int ch2 = (s2 >= 9) ? 1 : 0;
                issueA(s2 - ch2 * 9, ch2, s2 % 3);
                CP_COMMIT();
            }
        }

        uint32_t AH = su + A_BASE + buf * A_BUF_SZ + (uint32_t)(m_base * 144) + a_lane;
        uint32_t brow = (uint32_t)(((rr + ky) * 58 + kx) * 144);
        uint32_t XH = su + XT_H + brow;

        #pragma unroll
        for (int k = 0; k < 4; k++) {
            uint32_t ko = (uint32_t)(k * 32);
            uint32_t ah[2][4];
            ldsm4(AH + ko, ah[0]);
            ldsm4(AH + 2304 + ko, ah[1]);
            uint32_t bh[7][2];
            #pragma unroll
            for (int jj = 0; jj < 3; jj++)
                ldsm4b(XH + b4_lane + jj * 2304 + ko, bh[2 * jj], bh[2 * jj + 1]);
            ldsm2(XH + b2_lane + 6912 + ko, bh[6]);
            #pragma unroll
            for (int mt = 0; mt < 2; mt++)
                #pragma unroll
                for (int nt = 0; nt < 7; nt++)
                    mma16816(acc[mt][nt], ah[mt], bh[nt]);
        }
    }

    __syncthreads();
    // epilogue: 64 x 112 f32 via smem
    float* s_out = (float*)smem;
    int q = lane >> 2, l = lane & 3;
    int n_base = rr * 56;
    #pragma unroll
    for (int mt = 0; mt < 2; mt++)
        #pragma unroll
        for (int nt = 0; nt < 7; nt++) {
            int row = m_base + mt * 16 + q;
            int col = n_base + nt * 8 + l * 2;
            s_out[row * 112 + col] = acc[mt][nt][0];
            s_out[row * 112 + col + 1] = acc[mt][nt][1];
            s_out[(row + 8) * 112 + col] = acc[mt][nt][2];
            s_out[(row + 8) * 112 + col + 1] = acc[mt][nt][3];
        }
    __syncthreads();
    const float4* s4 = (const float4*)s_out;
    for (int i4 = tid; i4 < 64 * 28; i4 += 128) {
        int row = i4 / 28;
        int p4 = (i4 - row * 28) * 4;
        int co = h * 64 + row;
        *(float4*)&out[((size_t)(b * Cch + co)) * HWs + t * 112 + p4] = s4[i4];
    }
}

extern "C" void kernel_launch(void* const* d_in, const int* in_sizes, int n_in,
                              void* d_out, int out_size) {
    const float* x      = (const float*)d_in[0];
    const float* w_mask = (const float*)d_in[1];
    const float* b_mask = (const float*)d_in[2];
    const float* w1     = (const float*)d_in[3];
    const float* b1     = (const float*)d_in[4];
    const float* ln_g   = (const float*)d_in[5];
    const float* ln_b   = (const float*)d_in[6];
    const float* w2     = (const float*)d_in[7];
    const float* b2     = (const float*)d_in[8];
    const float* w_fc   = (const float*)d_in[9];
    const float* b_fc   = (const float*)d_in[10];
    float* out = (float*)d_out;

    cudaFuncSetAttribute(conv_kernel, cudaFuncAttributeMaxDynamicSharedMemorySize, SMEM_TOTAL);
    cudaFuncSetAttribute(prep_kernel, cudaFuncAttributeMaxDynamicSharedMemorySize, 36864);

    xT_kernel<<<dim3(58, Bn), 256>>>(x, w_mask, b_mask);
    ctx_kernel<<<dim3(4, Bn), 512>>>();
    prep_kernel<<<dim3(8, Bn), 256, 36864>>>(w1, b1, ln_g, ln_b, w2, b2, w_fc, b_fc);
    conv_kernel<<<dim3(28, 2, Bn), 128, SMEM_TOTAL>>>(out);
}

// round 14
// speedup vs baseline: 1.2533x; 1.0081x over previous
#include <cuda_runtime.h>
#include <cuda_fp16.h>
#include <math.h>
#include <stdint.h>

#define Bn 16
#define Cch 128
#define HWs 3136
#define Rr 16
#define MOc 256

// ---------------- device globals ----------------
__device__ float g_rowctx[Bn * 58 * Cch];   // per-row softmax-weighted ctx partials
__device__ float g_rowsum[Bn * 58];         // per-row exp sums
// per-(b,tap,chunk) weight tiles, row-major 128 cout x 64 cin fp16
__device__ __align__(16) __half g_wA_hi[16 * 18 * 8192];
// pixel-major padded fp16 x: [b][y 58][x 64][cin 128]
__device__ __align__(16) __half g_xT_h[16 * 58 * 64 * 128];

// ---------------- PTX helpers (target-portable, sm_80+) ----------------
__device__ __forceinline__ uint32_t smem_u32(const void* p) {
    uint32_t a;
    asm("{ .reg .u64 t; cvta.to.shared.u64 t, %1; cvt.u32.u64 %0, t; }" : "=r"(a) : "l"(p));
    return a;
}
__device__ __forceinline__ void ldsm4(uint32_t a, uint32_t* r) {
    asm volatile("ldmatrix.sync.aligned.m8n8.x4.shared.b16 {%0,%1,%2,%3}, [%4];"
                 : "=r"(r[0]), "=r"(r[1]), "=r"(r[2]), "=r"(r[3]) : "r"(a));
}
__device__ __forceinline__ void ldsm4b(uint32_t a, uint32_t* r0, uint32_t* r1) {
    asm volatile("ldmatrix.sync.aligned.m8n8.x4.shared.b16 {%0,%1,%2,%3}, [%4];"
                 : "=r"(r0[0]), "=r"(r0[1]), "=r"(r1[0]), "=r"(r1[1]) : "r"(a));
}
__device__ __forceinline__ void ldsm2(uint32_t a, uint32_t* r) {
    asm volatile("ldmatrix.sync.aligned.m8n8.x2.shared.b16 {%0,%1}, [%2];"
                 : "=r"(r[0]), "=r"(r[1]) : "r"(a));
}
__device__ __forceinline__ void mma16816(float* c, const uint32_t* a, const uint32_t* b) {
    asm volatile("mma.sync.aligned.m16n8k16.row.col.f32.f16.f16.f32 "
                 "{%0,%1,%2,%3}, {%4,%5,%6,%7}, {%8,%9}, {%0,%1,%2,%3};"
                 : "+f"(c[0]), "+f"(c[1]), "+f"(c[2]), "+f"(c[3])
                 : "r"(a[0]), "r"(a[1]), "r"(a[2]), "r"(a[3]), "r"(b[0]), "r"(b[1]));
}
__device__ __forceinline__ void cp16(uint32_t dst, const void* src) {
    asm volatile("cp.async.cg.shared.global [%0], [%1], 16;" :: "r"(dst), "l"(src));
}
#define CP_COMMIT() asm volatile("cp.async.commit_group;" ::: "memory")
#define CP_WAIT1() asm volatile("cp.async.wait_group 1;" ::: "memory")
#define CP_WAIT0() asm volatile("cp.async.wait_group 0;" ::: "memory")

// ---------------- Kernel 0: pad/transpose/fp16 x + fused mask->exp->row-partial ctx ----------------
// grid (58 padded rows, 16 batch), 256 threads.
__global__ void __launch_bounds__(256) xT_kernel(const float* __restrict__ x,
                                                 const float* __restrict__ w_mask,
                                                 const float* __restrict__ b_mask) {
    __shared__ float s_plane[Cch][56];
    __shared__ float s_wm[Cch];
    __shared__ float s_e[56];
    int y = blockIdx.x;                   // padded row: img y = y-1
    int b = blockIdx.y;
    int tid = threadIdx.x;
    int yi = y - 1;
    bool yv = (unsigned)yi < 56u;
    if (tid < Cch) s_wm[tid] = w_mask[tid];
    for (int i = tid; i < Cch * 56; i += 256) {
        int c = i / 56;
        int col = i - c * 56;
        s_plane[c][col] = yv ? x[((size_t)(b * Cch + c)) * HWs + yi * 56 + col] : 0.f;
    }
    __syncthreads();

    // exp(mask) for this row -- no max-subtraction (|mask| small; normalization cancels)
    if (tid < 56) {
        float m = b_mask[0];
        #pragma unroll 16
        for (int c = 0; c < Cch; c++) m = fmaf(s_plane[c][tid], s_wm[c], m);
        s_e[tid] = yv ? expf(m) : 0.f;
    }
    __syncthreads();

    if (tid == 0) {
        float s = 0.f;
        #pragma unroll
        for (int i = 0; i < 56; i++) s += s_e[i];
        g_rowsum[b * 58 + y] = s;
    }
    if (tid < Cch) {
        float acc = 0.f;
        #pragma unroll 8
        for (int col = 0; col < 56; col++) acc = fmaf(s_plane[tid][col], s_e[col], acc);
        g_rowctx[((size_t)(b * 58 + y)) * Cch + tid] = acc;
    }

    size_t rowbase = ((size_t)(b * 58 + y)) * 64 * 128;
    for (int i = tid; i < 1024; i += 256) {
        int x64 = i >> 4;
        int pc = i & 15;
        int cin0 = pc * 8;
        int ci = x64 - 1;
        bool cv = (unsigned)ci < 56u;
        unsigned int uh[4];
        #pragma unroll
        for (int q = 0; q < 4; q++) {
            unsigned int hw = 0;
            #pragma unroll
            for (int e = 0; e < 2; e++) {
                float v = cv ? s_plane[cin0 + q * 2 + e][ci] : 0.f;
                __half h = __float2half_rn(v);
                hw |= ((unsigned int)__half_as_ushort(h)) << (e * 16);
            }
            uh[q] = hw;
        }
        *(uint4*)(g_xT_h + rowbase + (size_t)x64 * 128 + cin0) = make_uint4(uh[0], uh[1], uh[2], uh[3]);
    }
}

// ---------------- Kernel 1: fused ctx-reduce + transform + weight-tile generation ----------------
// grid (8 cout-groups of 16, 16 batch), 256 threads.
__global__ void __launch_bounds__(256) prep_kernel(const float* __restrict__ w1,
                                                   const float* __restrict__ b1,
                                                   const float* __restrict__ ln_g,
                                                   const float* __restrict__ ln_b,
                                                   const float* __restrict__ w2,
                                                   const float* __restrict__ b2,
                                                   const float* __restrict__ w_fc,
                                                   const float* __restrict__ b_fc) {
    extern __shared__ __align__(16) char psm[];
    __half* s_h = (__half*)psm;                 // [18 tiles][16 co][64 cin]
    __shared__ float s_ctx[Cch];
    __shared__ float s_t[Rr];
    __shared__ float s_a[MOc];
    __shared__ float s_invS;
    int cog = blockIdx.x;
    int b = blockIdx.y;
    int tid = threadIdx.x;
    int co0 = cog * 16;

    if (tid < Cch) {
        const float* rp = g_rowctx + ((size_t)b * 58) * Cch + tid;
        float s = 0.f;
        #pragma unroll 8
        for (int y = 0; y < 58; y++) s += rp[(size_t)y * Cch];
        s_ctx[tid] = s;
    }
    if (tid == 128) {
        const float* rs = g_rowsum + b * 58;
        float S = 0.f;
        #pragma unroll
        for (int y = 0; y < 58; y++) S += rs[y];
        s_invS = 1.f / S;
    }
    __syncthreads();
    if (tid < Cch) s_ctx[tid] *= s_invS;
    __syncthreads();

    if (tid < Rr) {
        float acc = b1[tid];
        const float* wr = w1 + tid * Cch;
        #pragma unroll 16
        for (int c = 0; c < Cch; c++) acc = fmaf(s_ctx[c], wr[c], acc);
        s_t[tid] = acc;
    }
    __syncthreads();
    if (tid == 0) {
        float mu = 0.f;
        #pragma unroll
        for (int r = 0; r < Rr; r++) mu += s_t[r];
        mu *= (1.f / Rr);
        float var = 0.f;
        #pragma unroll
        for (int r = 0; r < Rr; r++) { float d = s_t[r] - mu; var = fmaf(d, d, var); }
        var *= (1.f / Rr);
        float invs = rsqrtf(var + 1e-5f);
        #pragma unroll
        for (int r = 0; r < Rr; r++) {
            float v = (s_t[r] - mu) * invs * ln_g[r] + ln_b[r];
            s_t[r] = fmaxf(v, 0.f);
        }
    }
    __syncthreads();
    {
        float acc = b2[tid];
        const float* wr = w2 + tid * Rr;
        #pragma unroll
        for (int r = 0; r < Rr; r++) acc = fmaf(s_t[r], wr[r], acc);
        s_a[tid] = 1.f / (1.f + expf(-acc));
    }
    __syncthreads();

    const float* wsrc = w_fc + (size_t)co0 * 1152;
    const float* bsrc = b_fc + (size_t)co0 * 1152;
    for (int i = tid; i < 16 * 1152; i += 256) {
        int co_l = i / 1152;
        int q = i - co_l * 1152;
        int cin = q / 9;
        int tap = q - cin * 9;
        int chunk = cin >> 6;
        int cl = cin & 63;
        float av = s_a[2 * (co0 + co_l) + chunk];
        float w = fmaf(av, wsrc[i], bsrc[i]);
        s_h[(tap * 2 + chunk) * 1024 + co_l * 64 + cl] = __float2half_rn(w);
    }
    __syncthreads();

    const uint4* sh4 = (const uint4*)s_h;
    for (int i = tid; i < 2304; i += 256) {
        int tile = i >> 7;
        int rem = i & 127;
        size_t dsto = ((size_t)(b * 18 + tile)) * 8192 + (size_t)(co0 + (rem >> 3)) * 64 + (rem & 7) * 8;
        *(uint4*)(g_wA_hi + dsto) = sh4[i];
    }
}

// ---------------- Kernel 2: HMMA conv, single-term fp16, M=64 half-tiles ----------------
// grid (28 row-pair tiles, 2 cout halves, 16 batch), 128 threads, 3 CTAs/SM.
#define XT_H       0
#define A_BASE     33792
#define A_BUF_SZ   9216
#define SMEM_TOTAL 61440

__global__ void __launch_bounds__(128, 3) conv_kernel(float* __restrict__ out) {
    extern __shared__ __align__(16) char smem[];
    uint32_t su = smem_u32(smem);
    int tid = threadIdx.x;
    int wid = tid >> 5;
    int lane = tid & 31;
    int t = blockIdx.x;
    int h = blockIdx.y;
    int b = blockIdx.z;

    int grp = lane >> 3, lr = lane & 7;
    int m_base = (wid & 1) * 32;
    int rr = wid >> 1;

    uint32_t a_lane = (uint32_t)((((grp & 1) * 8 + lr) * 144) + ((grp >> 1) * 16));
    uint32_t b4_lane = (uint32_t)((((grp >> 1) * 8 + lr) * 144) + ((grp & 1) * 16));
    int l16 = lane & 15;
    uint32_t b2_lane = (uint32_t)(((l16 & 7) * 144) + (((l16 >> 3) & 1) * 16));

    float acc[2][7][4];
    #pragma unroll
    for (int mt = 0; mt < 2; mt++)
        #pragma unroll
        for (int nt = 0; nt < 7; nt++)
            #pragma unroll
            for (int e = 0; e < 4; e++) acc[mt][nt][e] = 0.f;

    auto issueA = [&](int tap, int chunk, int bf) {
        size_t srco = ((size_t)(b * 18 + tap * 2 + chunk)) * 8192 + (size_t)h * 4096;
        const char* sh = (const char*)(g_wA_hi + srco);
        uint32_t dst = su + A_BASE + bf * A_BUF_SZ;
        for (int i = tid; i < 512; i += 128) {
            uint32_t doff = (uint32_t)((i >> 3) * 144 + (i & 7) * 16);
            cp16(dst + doff, sh + i * 16);
        }
    };
    auto issueXt = [&](int chunk) {
        size_t base = (((size_t)(b * 58 + 2 * t)) * 64) * 128 + chunk * 64;
        for (int i = tid; i < 1856; i += 128) {
            int j = i >> 3;
            int pcc = i & 7;
            int r = j / 58;
            int c = j - r * 58;
            uint32_t dst = su + (uint32_t)(j * 144 + pcc * 16);
            size_t srco = base + ((size_t)r * 64 + c) * 128 + pcc * 8;
            cp16(dst, (const char*)(g_xT_h + srco));
        }
    };

    // prologue: G[A0 + Xt0], G[A1]
    issueA(0, 0, 0);
    issueXt(0);
    CP_COMMIT();
    issueA(1, 0, 1);
    CP_COMMIT();

    for (int s = 0; s < 18; s++) {
        int chunk = (s >= 9) ? 1 : 0;
        int tap = s - chunk * 9;
        int ky = tap / 3;
        int kx = tap - ky * 3;
        int buf = s % 3;

        if (s == 9) {
            CP_WAIT1();
            __syncthreads();
            issueXt(1);
            issueA(2, 1, 11 % 3);        // A11 (tap 2, chunk 1)
            CP_COMMIT();
            CP_WAIT0();
            __syncthreads();
        } else if (s == 17) {
            CP_WAIT0();
            __syncthreads();
        } else {
            CP_WAIT1();
            __syncthreads();
            if (s < 16) {
                int s2 = s + 2;
                int ch2 = (s2 >= 9) ? 1 : 0;
                issueA(s2 - ch2 * 9, ch2, s2 % 3);
                CP_COMMIT();
            }
        }

        uint32_t AH = su + A_BASE + buf * A_BUF_SZ + (uint32_t)(m_base * 144) + a_lane;
        uint32_t brow = (uint32_t)(((rr + ky) * 58 + kx) * 144);
        uint32_t XH = su + XT_H + brow;

        #pragma unroll
        for (int k = 0; k < 4; k++) {
            uint32_t ko = (uint32_t)(k * 32);
            uint32_t ah[2][4];
            ldsm4(AH + ko, ah[0]);
            ldsm4(AH + 2304 + ko, ah[1]);
            uint32_t bh[7][2];
            #pragma unroll
            for (int jj = 0; jj < 3; jj++)
                ldsm4b(XH + b4_lane + jj * 2304 + ko, bh[2 * jj], bh[2 * jj + 1]);
            ldsm2(XH + b2_lane + 6912 + ko, bh[6]);
            #pragma unroll
            for (int mt = 0; mt < 2; mt++)
                #pragma unroll
                for (int nt = 0; nt < 7; nt++)
                    mma16816(acc[mt][nt], ah[mt], bh[nt]);
        }
    }

    __syncthreads();
    // epilogue: 64 x 112 f32 via smem
    float* s_out = (float*)smem;
    int q = lane >> 2, l = lane & 3;
    int n_base = rr * 56;
    #pragma unroll
    for (int mt = 0; mt < 2; mt++)
        #pragma unroll
        for (int nt = 0; nt < 7; nt++) {
            int row = m_base + mt * 16 + q;
            int col = n_base + nt * 8 + l * 2;
            s_out[row * 112 + col] = acc[mt][nt][0];
            s_out[row * 112 + col + 1] = acc[mt][nt][1];
            s_out[(row + 8) * 112 + col] = acc[mt][nt][2];
            s_out[(row + 8) * 112 + col + 1] = acc[mt][nt][3];
        }
    __syncthreads();
    const float4* s4 = (const float4*)s_out;
    for (int i4 = tid; i4 < 64 * 28; i4 += 128) {
        int row = i4 / 28;
        int p4 = (i4 - row * 28) * 4;
        int co = h * 64 + row;
        *(float4*)&out[((size_t)(b * Cch + co)) * HWs + t * 112 + p4] = s4[i4];
    }
}

extern "C" void kernel_launch(void* const* d_in, const int* in_sizes, int n_in,
                              void* d_out, int out_size) {
    const float* x      = (const float*)d_in[0];
    const float* w_mask = (const float*)d_in[1];
    const float* b_mask = (const float*)d_in[2];
    const float* w1     = (const float*)d_in[3];
    const float* b1     = (const float*)d_in[4];
    const float* ln_g   = (const float*)d_in[5];
    const float* ln_b   = (const float*)d_in[6];
    const float* w2     = (const float*)d_in[7];
    const float* b2     = (const float*)d_in[8];
    const float* w_fc   = (const float*)d_in[9];
    const float* b_fc   = (const float*)d_in[10];
    float* out = (float*)d_out;

    cudaFuncSetAttribute(conv_kernel, cudaFuncAttributeMaxDynamicSharedMemorySize, SMEM_TOTAL);
    cudaFuncSetAttribute(prep_kernel, cudaFuncAttributeMaxDynamicSharedMemorySize, 36864);

    xT_kernel<<<dim3(58, Bn), 256>>>(x, w_mask, b_mask);
    prep_kernel<<<dim3(8, Bn), 256, 36864>>>(w1, b1, ln_g, ln_b, w2, b2, w_fc, b_fc);
    conv_kernel<<<dim3(28, 2, Bn), 128, SMEM_TOTAL>>>(out);
}

// round 15
// speedup vs baseline: 1.4948x; 1.1926x over previous
#include <cuda_runtime.h>
#include <cuda_fp16.h>
#include <math.h>
#include <stdint.h>

#define Bn 16
#define Cch 128
#define HWs 3136
#define Rr 16
#define MOc 256
#define PLS 57   /* padded plane stride (odd) -> conflict-free/4-way smem access */

// ---------------- device globals ----------------
__device__ float g_rowctx[Bn * 58 * Cch];   // per-row softmax-weighted ctx partials
__device__ float g_rowsum[Bn * 58];         // per-row exp sums
// per-(b,tap,chunk) weight tiles, row-major 128 cout x 64 cin fp16
__device__ __align__(16) __half g_wA_hi[16 * 18 * 8192];
// pixel-major padded fp16 x: [b][y 58][x 64][cin 128]
__device__ __align__(16) __half g_xT_h[16 * 58 * 64 * 128];

// ---------------- PTX helpers (target-portable, sm_80+) ----------------
__device__ __forceinline__ uint32_t smem_u32(const void* p) {
    uint32_t a;
    asm("{ .reg .u64 t; cvta.to.shared.u64 t, %1; cvt.u32.u64 %0, t; }" : "=r"(a) : "l"(p));
    return a;
}
__device__ __forceinline__ void ldsm4(uint32_t a, uint32_t* r) {
    asm volatile("ldmatrix.sync.aligned.m8n8.x4.shared.b16 {%0,%1,%2,%3}, [%4];"
                 : "=r"(r[0]), "=r"(r[1]), "=r"(r[2]), "=r"(r[3]) : "r"(a));
}
__device__ __forceinline__ void ldsm4b(uint32_t a, uint32_t* r0, uint32_t* r1) {
    asm volatile("ldmatrix.sync.aligned.m8n8.x4.shared.b16 {%0,%1,%2,%3}, [%4];"
                 : "=r"(r0[0]), "=r"(r0[1]), "=r"(r1[0]), "=r"(r1[1]) : "r"(a));
}
__device__ __forceinline__ void ldsm2(uint32_t a, uint32_t* r) {
    asm volatile("ldmatrix.sync.aligned.m8n8.x2.shared.b16 {%0,%1}, [%2];"
                 : "=r"(r[0]), "=r"(r[1]) : "r"(a));
}
__device__ __forceinline__ void mma16816(float* c, const uint32_t* a, const uint32_t* b) {
    asm volatile("mma.sync.aligned.m16n8k16.row.col.f32.f16.f16.f32 "
                 "{%0,%1,%2,%3}, {%4,%5,%6,%7}, {%8,%9}, {%0,%1,%2,%3};"
                 : "+f"(c[0]), "+f"(c[1]), "+f"(c[2]), "+f"(c[3])
                 : "r"(a[0]), "r"(a[1]), "r"(a[2]), "r"(a[3]), "r"(b[0]), "r"(b[1]));
}
__device__ __forceinline__ void cp16(uint32_t dst, const void* src) {
    asm volatile("cp.async.cg.shared.global [%0], [%1], 16;" :: "r"(dst), "l"(src));
}
#define CP_COMMIT() asm volatile("cp.async.commit_group;" ::: "memory")
#define CP_WAIT1() asm volatile("cp.async.wait_group 1;" ::: "memory")
#define CP_WAIT0() asm volatile("cp.async.wait_group 0;" ::: "memory")

// ---------------- Kernel 0: pad/transpose/fp16 x + fused mask->exp->row-partial ctx ----------------
// grid (58 padded rows, 16 batch), 256 threads. s_plane padded to stride 57.
__global__ void __launch_bounds__(256) xT_kernel(const float* __restrict__ x,
                                                 const float* __restrict__ w_mask,
                                                 const float* __restrict__ b_mask) {
    __shared__ float s_plane[Cch][PLS];
    __shared__ float s_wm[Cch];
    __shared__ float s_e[56];
    int y = blockIdx.x;                   // padded row: img y = y-1
    int b = blockIdx.y;
    int tid = threadIdx.x;
    int yi = y - 1;
    bool yv = (unsigned)yi < 56u;
    if (tid < Cch) s_wm[tid] = w_mask[tid];
    for (int i = tid; i < Cch * 56; i += 256) {
        int c = i / 56;
        int col = i - c * 56;
        s_plane[c][col] = yv ? x[((size_t)(b * Cch + c)) * HWs + yi * 56 + col] : 0.f;
    }
    __syncthreads();

    // exp(mask) for this row -- no max-subtraction (|mask| small; normalization cancels)
    if (tid < 56) {
        float m = b_mask[0];
        #pragma unroll 16
        for (int c = 0; c < Cch; c++) m = fmaf(s_plane[c][tid], s_wm[c], m);
        s_e[tid] = yv ? expf(m) : 0.f;
    }
    __syncthreads();

    if (tid == 0) {
        float s = 0.f;
        #pragma unroll
        for (int i = 0; i < 56; i++) s += s_e[i];
        g_rowsum[b * 58 + y] = s;
    }
    if (tid < Cch) {
        float acc = 0.f;
        #pragma unroll 8
        for (int col = 0; col < 56; col++) acc = fmaf(s_plane[tid][col], s_e[col], acc);
        g_rowctx[((size_t)(b * 58 + y)) * Cch + tid] = acc;
    }

    size_t rowbase = ((size_t)(b * 58 + y)) * 64 * 128;
    for (int i = tid; i < 1024; i += 256) {
        int x64 = i >> 4;
        int pc = i & 15;
        int cin0 = pc * 8;
        int ci = x64 - 1;
        bool cv = (unsigned)ci < 56u;
        unsigned int uh[4];
        #pragma unroll
        for (int q = 0; q < 4; q++) {
            unsigned int hw = 0;
            #pragma unroll
            for (int e = 0; e < 2; e++) {
                float v = cv ? s_plane[cin0 + q * 2 + e][ci] : 0.f;
                __half h = __float2half_rn(v);
                hw |= ((unsigned int)__half_as_ushort(h)) << (e * 16);
            }
            uh[q] = hw;
        }
        *(uint4*)(g_xT_h + rowbase + (size_t)x64 * 128 + cin0) = make_uint4(uh[0], uh[1], uh[2], uh[3]);
    }
}

// ---------------- Kernel 1: fused ctx-reduce + transform + weight-tile generation ----------------
// grid (8 cout-groups of 16, 16 batch), 256 threads.
__global__ void __launch_bounds__(256) prep_kernel(const float* __restrict__ w1,
                                                   const float* __restrict__ b1,
                                                   const float* __restrict__ ln_g,
                                                   const float* __restrict__ ln_b,
                                                   const float* __restrict__ w2,
                                                   const float* __restrict__ b2,
                                                   const float* __restrict__ w_fc,
                                                   const float* __restrict__ b_fc) {
    extern __shared__ __align__(16) char psm[];
    __half* s_h = (__half*)psm;                 // [18 tiles][16 co][64 cin]
    __shared__ float s_ctx[Cch];
    __shared__ float s_t[Rr];
    __shared__ float s_a[MOc];
    __shared__ float s_invS;
    int cog = blockIdx.x;
    int b = blockIdx.y;
    int tid = threadIdx.x;
    int co0 = cog * 16;

    if (tid < Cch) {
        const float* rp = g_rowctx + ((size_t)b * 58) * Cch + tid;
        float s = 0.f;
        #pragma unroll 8
        for (int y = 0; y < 58; y++) s += rp[(size_t)y * Cch];
        s_ctx[tid] = s;
    }
    if (tid == 128) {
        const float* rs = g_rowsum + b * 58;
        float S = 0.f;
        #pragma unroll
        for (int y = 0; y < 58; y++) S += rs[y];
        s_invS = 1.f / S;
    }
    __syncthreads();
    if (tid < Cch) s_ctx[tid] *= s_invS;
    __syncthreads();

    if (tid < Rr) {
        float acc = b1[tid];
        const float* wr = w1 + tid * Cch;
        #pragma unroll 16
        for (int c = 0; c < Cch; c++) acc = fmaf(s_ctx[c], wr[c], acc);
        s_t[tid] = acc;
    }
    __syncthreads();
    if (tid == 0) {
        float mu = 0.f;
        #pragma unroll
        for (int r = 0; r < Rr; r++) mu += s_t[r];
        mu *= (1.f / Rr);
        float var = 0.f;
        #pragma unroll
        for (int r = 0; r < Rr; r++) { float d = s_t[r] - mu; var = fmaf(d, d, var); }
        var *= (1.f / Rr);
        float invs = rsqrtf(var + 1e-5f);
        #pragma unroll
        for (int r = 0; r < Rr; r++) {
            float v = (s_t[r] - mu) * invs * ln_g[r] + ln_b[r];
            s_t[r] = fmaxf(v, 0.f);
        }
    }
    __syncthreads();
    {
        float acc = b2[tid];
        const float* wr = w2 + tid * Rr;
        #pragma unroll
        for (int r = 0; r < Rr; r++) acc = fmaf(s_t[r], wr[r], acc);
        s_a[tid] = 1.f / (1.f + expf(-acc));
    }
    __syncthreads();

    const float* wsrc = w_fc + (size_t)co0 * 1152;
    const float* bsrc = b_fc + (size_t)co0 * 1152;
    for (int i = tid; i < 16 * 1152; i += 256) {
        int co_l = i / 1152;
        int q = i - co_l * 1152;
        int cin = q / 9;
        int tap = q - cin * 9;
        int chunk = cin >> 6;
        int cl = cin & 63;
        float av = s_a[2 * (co0 + co_l) + chunk];
        float w = fmaf(av, wsrc[i], bsrc[i]);
        s_h[(tap * 2 + chunk) * 1024 + co_l * 64 + cl] = __float2half_rn(w);
    }
    __syncthreads();

    const uint4* sh4 = (const uint4*)s_h;
    for (int i = tid; i < 2304; i += 256) {
        int tile = i >> 7;
        int rem = i & 127;
        size_t dsto = ((size_t)(b * 18 + tile)) * 8192 + (size_t)(co0 + (rem >> 3)) * 64 + (rem & 7) * 8;
        *(uint4*)(g_wA_hi + dsto) = sh4[i];
    }
}

// ---------------- Kernel 2: HMMA conv, single-term fp16, M=64 half-tiles ----------------
// grid (28 row-pair tiles, 2 cout halves, 16 batch), 128 threads, 3 CTAs/SM.
#define XT_H       0
#define A_BASE     33792
#define A_BUF_SZ   9216
#define SMEM_TOTAL 61440

__global__ void __launch_bounds__(128, 3) conv_kernel(float* __restrict__ out) {
    extern __shared__ __align__(16) char smem[];
    uint32_t su = smem_u32(smem);
    int tid = threadIdx.x;
    int wid = tid >> 5;
    int lane = tid & 31;
    int t = blockIdx.x;
    int h = blockIdx.y;
    int b = blockIdx.z;

    int grp = lane >> 3, lr = lane & 7;
    int m_base = (wid & 1) * 32;
    int rr = wid >> 1;

    uint32_t a_lane = (uint32_t)((((grp & 1) * 8 + lr) * 144) + ((grp >> 1) * 16));
    uint32_t b4_lane = (uint32_t)((((grp >> 1) * 8 + lr) * 144) + ((grp & 1) * 16));
    int l16 = lane & 15;
    uint32_t b2_lane = (uint32_t)(((l16 & 7) * 144) + (((l16 >> 3) & 1) * 16));

    float acc[2][7][4];
    #pragma unroll
    for (int mt = 0; mt < 2; mt++)
        #pragma unroll
        for (int nt = 0; nt < 7; nt++)
            #pragma unroll
            for (int e = 0; e < 4; e++) acc[mt][nt][e] = 0.f;

    auto issueA = [&](int tap, int chunk, int bf) {
        size_t srco = ((size_t)(b * 18 + tap * 2 + chunk)) * 8192 + (size_t)h * 4096;
        const char* sh = (const char*)(g_wA_hi + srco);
        uint32_t dst = su + A_BASE + bf * A_BUF_SZ;
        for (int i = tid; i < 512; i += 128) {
            uint32_t doff = (uint32_t)((i >> 3) * 144 + (i & 7) * 16);
            cp16(dst + doff, sh + i * 16);
        }
    };
    auto issueXt = [&](int chunk) {
        size_t base = (((size_t)(b * 58 + 2 * t)) * 64) * 128 + chunk * 64;
        for (int i = tid; i < 1856; i += 128) {
            int j = i >> 3;
            int pcc = i & 7;
            int r = j / 58;
            int c = j - r * 58;
            uint32_t dst = su + (uint32_t)(j * 144 + pcc * 16);
            size_t srco = base + ((size_t)r * 64 + c) * 128 + pcc * 8;
            cp16(dst, (const char*)(g_xT_h + srco));
        }
    };

    // prologue: G[A0 + Xt0], G[A1]
    issueA(0, 0, 0);
    issueXt(0);
    CP_COMMIT();
    issueA(1, 0, 1);
    CP_COMMIT();

    for (int s = 0; s < 18; s++) {
        int chunk = (s >= 9) ? 1 : 0;
        int tap = s - chunk * 9;
        int ky = tap / 3;
        int kx = tap - ky * 3;
        int buf = s % 3;

        if (s == 9) {
            CP_WAIT1();
            __syncthreads();
            issueXt(1);
            issueA(2, 1, 11 % 3);        // A11 (tap 2, chunk 1)
            CP_COMMIT();
            CP_WAIT0();
            __syncthreads();
        } else if (s == 17) {
            CP_WAIT0();
            __syncthreads();
        } else {
            CP_WAIT1();
            __syncthreads();
            if (s < 16) {
                int s2 = s + 2;
                int ch2 = (s2 >= 9) ? 1 : 0;
                issueA(s2 - ch2 * 9, ch2, s2 % 3);
                CP_COMMIT();
            }
        }

        uint32_t AH = su + A_BASE + buf * A_BUF_SZ + (uint32_t)(m_base * 144) + a_lane;
        uint32_t brow = (uint32_t)(((rr + ky) * 58 + kx) * 144);
        uint32_t XH = su + XT_H + brow;

        #pragma unroll
        for (int k = 0; k < 4; k++) {
            uint32_t ko = (uint32_t)(k * 32);
            uint32_t ah[2][4];
            ldsm4(AH + ko, ah[0]);
            ldsm4(AH + 2304 + ko, ah[1]);
            uint32_t bh[7][2];
            #pragma unroll
            for (int jj = 0; jj < 3; jj++)
                ldsm4b(XH + b4_lane + jj * 2304 + ko, bh[2 * jj], bh[2 * jj + 1]);
            ldsm2(XH + b2_lane + 6912 + ko, bh[6]);
            #pragma unroll
            for (int mt = 0; mt < 2; mt++)
                #pragma unroll
                for (int nt = 0; nt < 7; nt++)
                    mma16816(acc[mt][nt], ah[mt], bh[nt]);
        }
    }

    __syncthreads();
    // epilogue: 64 x 112 f32 via smem
    float* s_out = (float*)smem;
    int q = lane >> 2, l = lane & 3;
    int n_base = rr * 56;
    #pragma unroll
    for (int mt = 0; mt < 2; mt++)
        #pragma unroll
        for (int nt = 0; nt < 7; nt++) {
            int row = m_base + mt * 16 + q;
            int col = n_base + nt * 8 + l * 2;
            s_out[row * 112 + col] = acc[mt][nt][0];
            s_out[row * 112 + col + 1] = acc[mt][nt][1];
            s_out[(row + 8) * 112 + col] = acc[mt][nt][2];
            s_out[(row + 8) * 112 + col + 1] = acc[mt][nt][3];
        }
    __syncthreads();
    const float4* s4 = (const float4*)s_out;
    for (int i4 = tid; i4 < 64 * 28; i4 += 128) {
        int row = i4 / 28;
        int p4 = (i4 - row * 28) * 4;
        int co = h * 64 + row;
        *(float4*)&out[((size_t)(b * Cch + co)) * HWs + t * 112 + p4] = s4[i4];
    }
}

extern "C" void kernel_launch(void* const* d_in, const int* in_sizes, int n_in,
                              void* d_out, int out_size) {
    const float* x      = (const float*)d_in[0];
    const float* w_mask = (const float*)d_in[1];
    const float* b_mask = (const float*)d_in[2];
    const float* w1     = (const float*)d_in[3];
    const float* b1     = (const float*)d_in[4];
    const float* ln_g   = (const float*)d_in[5];
    const float* ln_b   = (const float*)d_in[6];
    const float* w2     = (const float*)d_in[7];
    const float* b2     = (const float*)d_in[8];
    const float* w_fc   = (const float*)d_in[9];
    const float* b_fc   = (const float*)d_in[10];
    float* out = (float*)d_out;

    cudaFuncSetAttribute(conv_kernel, cudaFuncAttributeMaxDynamicSharedMemorySize, SMEM_TOTAL);
    cudaFuncSetAttribute(prep_kernel, cudaFuncAttributeMaxDynamicSharedMemorySize, 36864);

    xT_kernel<<<dim3(58, Bn), 256>>>(x, w_mask, b_mask);
    prep_kernel<<<dim3(8, Bn), 256, 36864>>>(w1, b1, ln_g, ln_b, w2, b2, w_fc, b_fc);
    conv_kernel<<<dim3(28, 2, Bn), 128, SMEM_TOTAL>>>(out);
}